// round 1
// baseline (speedup 1.0000x reference)
#include <cuda_runtime.h>
#include <math.h>
#include <stdint.h>

// ---------------- problem constants ----------------
#define NN   50000   // nodes
#define EE   400000  // edges per relation
#define RR   3       // relations
#define FIN  128     // input features
#define FHID 64      // hidden features
#define FC   40      // classes
#define NH   3       // heads
#define NEG_SLOPE 0.2f

// ---------------- scratch (static device buffer; no allocations allowed) ----
// z1: 3*50000*192 f32      = 115.2 MB
// z2: 3*50000*120 f32      =  72.0 MB
// el1/er1/el2/er2: 450k f32 each
// h:  50000*64 f32         =  12.8 MB
// cnt/ptr/cur/csrc ints    ~   6.6 MB
#define SCRATCH_BYTES (232ull * 1024 * 1024)
__device__ __align__(256) unsigned char g_scratch[SCRATCH_BYTES];

__device__ __forceinline__ float lrelu(float x) { return x > 0.f ? x : NEG_SLOPE * x; }

// ---------------- CSR build ----------------
__global__ void zero_k(int* p, int nitems) {
    int i = blockIdx.x * blockDim.x + threadIdx.x;
    if (i < nitems) p[i] = 0;
}

__global__ void count_k(const int* __restrict__ dst, int* __restrict__ cnt) {
    int i = blockIdx.x * blockDim.x + threadIdx.x;
    if (i >= RR * EE) return;
    int r = i / EE;
    atomicAdd(&cnt[r * NN + dst[i]], 1);
}

// one block (1024 threads) per relation: exclusive scan of counts -> ptr, cur
__global__ void scan_k(const int* __restrict__ cnt, int* __restrict__ ptr, int* __restrict__ cur) {
    const int r = blockIdx.x;
    const int t = threadIdx.x;
    const int CH = (NN + 1023) / 1024;
    int s0 = t * CH;
    int s1 = s0 + CH; if (s1 > NN) s1 = NN;
    if (s0 > NN) s0 = NN;
    int sum = 0;
    for (int n = s0; n < s1; n++) sum += cnt[r * NN + n];
    __shared__ int sh[1024];
    sh[t] = sum;
    __syncthreads();
    for (int off = 1; off < 1024; off <<= 1) {
        int v = (t >= off) ? sh[t - off] : 0;
        __syncthreads();
        sh[t] += v;
        __syncthreads();
    }
    int base = sh[t] - sum;  // exclusive prefix
    for (int n = s0; n < s1; n++) {
        ptr[r * (NN + 1) + n] = base;
        cur[r * NN + n] = base;
        base += cnt[r * NN + n];
    }
    if (t == 1023) ptr[r * (NN + 1) + NN] = sh[1023];
}

__global__ void scatter_k(const int* __restrict__ src, const int* __restrict__ dst,
                          int* __restrict__ cur, int* __restrict__ csrc) {
    int i = blockIdx.x * blockDim.x + threadIdx.x;
    if (i >= RR * EE) return;
    int r = i / EE;
    int d = dst[i];
    int pos = atomicAdd(&cur[r * NN + d], 1);    // within-relation position
    csrc[(size_t)r * EE + pos] = src[i];
}

// ---------------- SGEMM: C_r = A @ B_r, B batched over relations (blockIdx.z)
// BM=128, BN=64, BK=16, 256 threads, 8x4 microtile.
__global__ void sgemm_k(const float* __restrict__ A, const float* __restrict__ B,
                        float* __restrict__ C, int nrows, int K, int M) {
    __shared__ float As[16][128];
    __shared__ float Bs[16][64];
    const int r = blockIdx.z;
    const float* Br = B + (size_t)r * K * M;
    float* Cr = C + (size_t)r * nrows * M;
    const int rowBase = blockIdx.y * 128;
    const int colBase = blockIdx.x * 64;
    const int tid = threadIdx.x;
    const int ty = tid >> 4, tx = tid & 15;
    const int ar = tid >> 2, ac = (tid & 3) * 4;   // A loader: rows ar, ar+64; k cols ac..ac+3
    const int bk = tid >> 4, bc = (tid & 15) * 4;  // B loader

    float acc[8][4];
#pragma unroll
    for (int i = 0; i < 8; i++)
#pragma unroll
        for (int j = 0; j < 4; j++) acc[i][j] = 0.f;

    for (int k0 = 0; k0 < K; k0 += 16) {
#pragma unroll
        for (int half = 0; half < 2; half++) {
            int row = ar + half * 64;
            int grow = rowBase + row;
            float4 v = make_float4(0.f, 0.f, 0.f, 0.f);
            if (grow < nrows) v = *(const float4*)(A + (size_t)grow * K + k0 + ac);
            As[ac + 0][row] = v.x;
            As[ac + 1][row] = v.y;
            As[ac + 2][row] = v.z;
            As[ac + 3][row] = v.w;
        }
        {
            int gk = k0 + bk;
#pragma unroll
            for (int j = 0; j < 4; j++) {
                int gc = colBase + bc + j;
                Bs[bk][bc + j] = (gc < M) ? Br[(size_t)gk * M + gc] : 0.f;
            }
        }
        __syncthreads();
#pragma unroll
        for (int kk = 0; kk < 16; kk++) {
            float4 b4 = *(const float4*)&Bs[kk][tx * 4];
            float4 a0 = *(const float4*)&As[kk][ty * 8];
            float4 a1 = *(const float4*)&As[kk][ty * 8 + 4];
            float a[8] = {a0.x, a0.y, a0.z, a0.w, a1.x, a1.y, a1.z, a1.w};
            float b[4] = {b4.x, b4.y, b4.z, b4.w};
#pragma unroll
            for (int i = 0; i < 8; i++)
#pragma unroll
                for (int j = 0; j < 4; j++) acc[i][j] += a[i] * b[j];
        }
        __syncthreads();
    }
#pragma unroll
    for (int i = 0; i < 8; i++) {
        int grow = rowBase + ty * 8 + i;
        int gc = colBase + tx * 4;
        if (grow < nrows && gc < M) {
            float4 v = make_float4(acc[i][0], acc[i][1], acc[i][2], acc[i][3]);
            *(float4*)(Cr + (size_t)grow * M + gc) = v;
        }
    }
}

// ---------------- attention coefficients: el/er per (r,node,head) ----------
template <int HOUT>
__global__ void attn_k(const float* __restrict__ z, const float* __restrict__ al,
                       const float* __restrict__ ar, float* __restrict__ el,
                       float* __restrict__ er) {
    int w = (blockIdx.x * blockDim.x + threadIdx.x) >> 5;
    int lane = threadIdx.x & 31;
    if (w >= RR * NN) return;
    int r = w / NN;
    const int TOT = NH * HOUT;
    const float* zr = z + (size_t)w * TOT;
    float aL0 = 0, aL1 = 0, aL2 = 0, aR0 = 0, aR1 = 0, aR2 = 0;
    for (int j = lane; j < TOT; j += 32) {
        int h = j / HOUT, c = j % HOUT;
        float v = zr[j];
        float wl = al[((size_t)r * NH + h) * HOUT + c];
        float wr = ar[((size_t)r * NH + h) * HOUT + c];
        if (h == 0) { aL0 += v * wl; aR0 += v * wr; }
        else if (h == 1) { aL1 += v * wl; aR1 += v * wr; }
        else { aL2 += v * wl; aR2 += v * wr; }
    }
#pragma unroll
    for (int o = 16; o; o >>= 1) {
        aL0 += __shfl_xor_sync(0xffffffffu, aL0, o);
        aL1 += __shfl_xor_sync(0xffffffffu, aL1, o);
        aL2 += __shfl_xor_sync(0xffffffffu, aL2, o);
        aR0 += __shfl_xor_sync(0xffffffffu, aR0, o);
        aR1 += __shfl_xor_sync(0xffffffffu, aR1, o);
        aR2 += __shfl_xor_sync(0xffffffffu, aR2, o);
    }
    if (lane == 0) {
        size_t o = (size_t)w * NH;
        el[o] = aL0; el[o + 1] = aL1; el[o + 2] = aL2;
        er[o] = aR0; er[o + 1] = aR1; er[o + 2] = aR2;
    }
}

// ---------------- fused edge-softmax + aggregation + head/relation mean ----
// one warp per dst node; loops relations; CSR gather (no atomics).
template <int OUT, bool RELU>
__global__ void agg_k(const float* __restrict__ z, const float* __restrict__ el,
                      const float* __restrict__ er, const float* __restrict__ bias,
                      const int* __restrict__ ptr, const int* __restrict__ csrc,
                      float* __restrict__ out) {
    int w = (blockIdx.x * blockDim.x + threadIdx.x) >> 5;
    int lane = threadIdx.x & 31;
    if (w >= NN) return;
    const int n = w;
    float tot0 = 0.f, tot1 = 0.f;
    for (int r = 0; r < RR; r++) {
        const float* elr = el + (size_t)r * NN * NH;
        const float* ern = er + ((size_t)r * NN + n) * NH;
        float er0 = ern[0], er1 = ern[1], er2 = ern[2];
        int beg = ptr[r * (NN + 1) + n];
        int end = ptr[r * (NN + 1) + n + 1];
        const int* cs = csrc + (size_t)r * EE;

        // pass 1: per-head max over incoming edges
        float m0 = -1e30f, m1 = -1e30f, m2 = -1e30f;
        for (int i = beg + lane; i < end; i += 32) {
            const float* e3 = elr + (size_t)cs[i] * NH;
            m0 = fmaxf(m0, lrelu(e3[0] + er0));
            m1 = fmaxf(m1, lrelu(e3[1] + er1));
            m2 = fmaxf(m2, lrelu(e3[2] + er2));
        }
#pragma unroll
        for (int o = 16; o; o >>= 1) {
            m0 = fmaxf(m0, __shfl_xor_sync(0xffffffffu, m0, o));
            m1 = fmaxf(m1, __shfl_xor_sync(0xffffffffu, m1, o));
            m2 = fmaxf(m2, __shfl_xor_sync(0xffffffffu, m2, o));
        }
        // pass 2: per-head sum of exp
        float s0 = 0.f, s1 = 0.f, s2 = 0.f;
        for (int i = beg + lane; i < end; i += 32) {
            const float* e3 = elr + (size_t)cs[i] * NH;
            s0 += expf(lrelu(e3[0] + er0) - m0);
            s1 += expf(lrelu(e3[1] + er1) - m1);
            s2 += expf(lrelu(e3[2] + er2) - m2);
        }
#pragma unroll
        for (int o = 16; o; o >>= 1) {
            s0 += __shfl_xor_sync(0xffffffffu, s0, o);
            s1 += __shfl_xor_sync(0xffffffffu, s1, o);
            s2 += __shfl_xor_sync(0xffffffffu, s2, o);
        }
        float inv0 = (end > beg) ? 1.f / s0 : 0.f;
        float inv1 = (end > beg) ? 1.f / s1 : 0.f;
        float inv2 = (end > beg) ? 1.f / s2 : 0.f;

        // pass 3: weighted gather of z[src]; lanes own output columns
        float a00 = 0, a01 = 0, a10 = 0, a11 = 0, a20 = 0, a21 = 0;
        for (int i = beg; i < end; i++) {
            int s = cs[i];  // uniform across warp
            const float* e3 = elr + (size_t)s * NH;
            float al0 = expf(lrelu(e3[0] + er0) - m0) * inv0;
            float al1 = expf(lrelu(e3[1] + er1) - m1) * inv1;
            float al2 = expf(lrelu(e3[2] + er2) - m2) * inv2;
            const float* zr = z + ((size_t)r * NN + s) * (NH * OUT);
            a00 += al0 * zr[0 * OUT + lane];
            a10 += al1 * zr[1 * OUT + lane];
            a20 += al2 * zr[2 * OUT + lane];
            if (lane + 32 < OUT) {
                a01 += al0 * zr[0 * OUT + lane + 32];
                a11 += al1 * zr[1 * OUT + lane + 32];
                a21 += al2 * zr[2 * OUT + lane + 32];
            }
        }
        // bias + (relu) + head mean
        const float* br = bias + (size_t)r * NH * OUT;
        {
            float t0 = a00 + br[0 * OUT + lane];
            float t1 = a10 + br[1 * OUT + lane];
            float t2 = a20 + br[2 * OUT + lane];
            if (RELU) { t0 = fmaxf(t0, 0.f); t1 = fmaxf(t1, 0.f); t2 = fmaxf(t2, 0.f); }
            tot0 += (t0 + t1 + t2) * (1.f / NH);
        }
        if (lane + 32 < OUT) {
            float t0 = a01 + br[0 * OUT + lane + 32];
            float t1 = a11 + br[1 * OUT + lane + 32];
            float t2 = a21 + br[2 * OUT + lane + 32];
            if (RELU) { t0 = fmaxf(t0, 0.f); t1 = fmaxf(t1, 0.f); t2 = fmaxf(t2, 0.f); }
            tot1 += (t0 + t1 + t2) * (1.f / NH);
        }
    }
    out[(size_t)n * OUT + lane] = tot0 * (1.f / RR);
    if (lane + 32 < OUT) out[(size_t)n * OUT + lane + 32] = tot1 * (1.f / RR);
}

// ---------------- launch ----------------
extern "C" void kernel_launch(void* const* d_in, const int* in_sizes, int n_in,
                              void* d_out, int out_size) {
    const float* feat = (const float*)d_in[0];
    const int*   src  = (const int*)d_in[1];
    const int*   dst  = (const int*)d_in[2];
    const float* W1   = (const float*)d_in[3];
    const float* al1  = (const float*)d_in[4];
    const float* ar1  = (const float*)d_in[5];
    const float* b1   = (const float*)d_in[6];
    const float* W2   = (const float*)d_in[7];
    const float* al2  = (const float*)d_in[8];
    const float* ar2  = (const float*)d_in[9];
    const float* b2   = (const float*)d_in[10];
    float* out = (float*)d_out;

    unsigned char* base = nullptr;
    cudaGetSymbolAddress((void**)&base, g_scratch);

    size_t off = 0;
    auto carve = [&](size_t bytes) -> unsigned char* {
        unsigned char* p = base + off;
        off += (bytes + 255) & ~(size_t)255;
        return p;
    };
    float* z1  = (float*)carve((size_t)RR * NN * NH * FHID * 4);
    float* z2  = (float*)carve((size_t)RR * NN * NH * FC * 4);
    float* el1 = (float*)carve((size_t)RR * NN * NH * 4);
    float* er1 = (float*)carve((size_t)RR * NN * NH * 4);
    float* el2 = (float*)carve((size_t)RR * NN * NH * 4);
    float* er2 = (float*)carve((size_t)RR * NN * NH * 4);
    float* hbuf = (float*)carve((size_t)NN * FHID * 4);
    int* cnt  = (int*)carve((size_t)RR * NN * 4);
    int* ptr  = (int*)carve((size_t)RR * (NN + 1) * 4);
    int* cur  = (int*)carve((size_t)RR * NN * 4);
    int* csrc = (int*)carve((size_t)RR * EE * 4);

    // ---- CSR build (shared by both layers) ----
    zero_k<<<(RR * NN + 255) / 256, 256>>>(cnt, RR * NN);
    count_k<<<(RR * EE + 255) / 256, 256>>>(dst, cnt);
    scan_k<<<RR, 1024>>>(cnt, ptr, cur);
    scatter_k<<<(RR * EE + 255) / 256, 256>>>(src, dst, cur, csrc);

    // ---- layer 1 ----
    {
        dim3 grid((NH * FHID + 63) / 64, (NN + 127) / 128, RR);
        sgemm_k<<<grid, 256>>>(feat, W1, z1, NN, FIN, NH * FHID);
    }
    attn_k<FHID><<<(RR * NN * 32 + 255) / 256, 256>>>(z1, al1, ar1, el1, er1);
    agg_k<FHID, true><<<(NN * 32 + 255) / 256, 256>>>(z1, el1, er1, b1, ptr, csrc, hbuf);

    // ---- layer 2 ----
    {
        dim3 grid((NH * FC + 63) / 64, (NN + 127) / 128, RR);
        sgemm_k<<<grid, 256>>>(hbuf, W2, z2, NN, FHID, NH * FC);
    }
    attn_k<FC><<<(RR * NN * 32 + 255) / 256, 256>>>(z2, al2, ar2, el2, er2);
    agg_k<FC, false><<<(NN * 32 + 255) / 256, 256>>>(z2, el2, er2, b2, ptr, csrc, out);

    (void)in_sizes; (void)n_in; (void)out_size;
}

// round 2
// speedup vs baseline: 1.1084x; 1.1084x over previous
#include <cuda_runtime.h>
#include <cuda_bf16.h>
#include <math.h>
#include <stdint.h>

// ---------------- problem constants ----------------
#define NN   50000   // nodes
#define EE   400000  // edges per relation
#define RR   3       // relations
#define FIN  128     // input features
#define FHID 64      // hidden features
#define FC   40      // classes
#define NH   3       // heads
#define NEG_SLOPE 0.2f

#define SCRATCH_BYTES (288ull * 1024 * 1024)
__device__ __align__(256) unsigned char g_scratch[SCRATCH_BYTES];

__device__ __forceinline__ float lrelu(float x) { return x > 0.f ? x : NEG_SLOPE * x; }

// ---------------- CSR build ----------------
__global__ void zero_k(int* p, int nitems) {
    int i = blockIdx.x * blockDim.x + threadIdx.x;
    if (i < nitems) p[i] = 0;
}

__global__ void count_k(const int* __restrict__ dst, int* __restrict__ cnt) {
    int i = blockIdx.x * blockDim.x + threadIdx.x;
    if (i >= RR * EE) return;
    int r = i / EE;
    atomicAdd(&cnt[r * NN + dst[i]], 1);
}

__global__ void scan_k(const int* __restrict__ cnt, int* __restrict__ ptr, int* __restrict__ cur) {
    const int r = blockIdx.x;
    const int t = threadIdx.x;
    const int CH = (NN + 1023) / 1024;
    int s0 = t * CH;
    int s1 = s0 + CH; if (s1 > NN) s1 = NN;
    if (s0 > NN) s0 = NN;
    int sum = 0;
    for (int n = s0; n < s1; n++) sum += cnt[r * NN + n];
    __shared__ int sh[1024];
    sh[t] = sum;
    __syncthreads();
    for (int off = 1; off < 1024; off <<= 1) {
        int v = (t >= off) ? sh[t - off] : 0;
        __syncthreads();
        sh[t] += v;
        __syncthreads();
    }
    int base = sh[t] - sum;
    for (int n = s0; n < s1; n++) {
        ptr[r * (NN + 1) + n] = base;
        cur[r * NN + n] = base;
        base += cnt[r * NN + n];
    }
    if (t == 1023) ptr[r * (NN + 1) + NN] = sh[1023];
}

__global__ void scatter_k(const int* __restrict__ src, const int* __restrict__ dst,
                          int* __restrict__ cur, int* __restrict__ csrc) {
    int i = blockIdx.x * blockDim.x + threadIdx.x;
    if (i >= RR * EE) return;
    int r = i / EE;
    int d = dst[i];
    int pos = atomicAdd(&cur[r * NN + d], 1);
    csrc[(size_t)r * EE + pos] = src[i];
}

// ---------------- fp32 -> (bf16 hi, bf16 lo) split ----------------
__global__ void split_k(const float* __restrict__ in, __nv_bfloat16* __restrict__ hi,
                        __nv_bfloat16* __restrict__ lo, int n4) {
    int i = blockIdx.x * blockDim.x + threadIdx.x;
    if (i >= n4) return;
    float4 v = ((const float4*)in)[i];
    __nv_bfloat16 h0 = __float2bfloat16(v.x), h1 = __float2bfloat16(v.y);
    __nv_bfloat16 h2 = __float2bfloat16(v.z), h3 = __float2bfloat16(v.w);
    __nv_bfloat162 hh0, hh1, ll0, ll1;
    hh0.x = h0; hh0.y = h1; hh1.x = h2; hh1.y = h3;
    ll0.x = __float2bfloat16(v.x - __bfloat162float(h0));
    ll0.y = __float2bfloat16(v.y - __bfloat162float(h1));
    ll1.x = __float2bfloat16(v.z - __bfloat162float(h2));
    ll1.y = __float2bfloat16(v.w - __bfloat162float(h3));
    ((__nv_bfloat162*)hi)[i * 2 + 0] = hh0;
    ((__nv_bfloat162*)hi)[i * 2 + 1] = hh1;
    ((__nv_bfloat162*)lo)[i * 2 + 0] = ll0;
    ((__nv_bfloat162*)lo)[i * 2 + 1] = ll1;
}

// ---------------- tensor-core GEMM (bf16 hi/lo split, fp32-accurate) --------
// C_r[row][col] = sum_k A[row][k] * W_r[k][col]
// Block: 256 thr (8 warps), tile 128 rows x 64 cols, full K resident in smem.
__device__ __forceinline__ void mma16816(float* c, const uint32_t* a, uint32_t b0, uint32_t b1) {
    asm volatile(
        "mma.sync.aligned.m16n8k16.row.col.f32.bf16.bf16.f32 "
        "{%0,%1,%2,%3}, {%4,%5,%6,%7}, {%8,%9}, {%0,%1,%2,%3};"
        : "+f"(c[0]), "+f"(c[1]), "+f"(c[2]), "+f"(c[3])
        : "r"(a[0]), "r"(a[1]), "r"(a[2]), "r"(a[3]), "r"(b0), "r"(b1));
}

template <int K>
__global__ void gemm_bf16_k(const __nv_bfloat16* __restrict__ Ahi,
                            const __nv_bfloat16* __restrict__ Alo,
                            const float* __restrict__ W, float* __restrict__ C,
                            int nrows, int M) {
    constexpr int KP = K + 8;  // padded stride (bank-conflict-free fragments)
    extern __shared__ __nv_bfloat16 sm[];
    __nv_bfloat16* Ah = sm;                  // [128][KP]
    __nv_bfloat16* Al = Ah + 128 * KP;       // [128][KP]
    __nv_bfloat16* Bh = Al + 128 * KP;       // [64][KP]  (col-major by n)
    __nv_bfloat16* Bl = Bh + 64 * KP;        // [64][KP]

    const int r = blockIdx.z;
    const float* Wr = W + (size_t)r * K * M;
    float* Cr = C + (size_t)r * nrows * M;
    const int rowBase = blockIdx.y * 128;
    const int colBase = blockIdx.x * 64;
    const int tid = threadIdx.x;

    // load A tile (hi & lo), 16B chunks of 8 bf16
    constexpr int CPR = K / 8;               // chunks per row
    for (int c = tid; c < 128 * CPR; c += 256) {
        int row = c / CPR;
        int cb = c % CPR;
        int grow = rowBase + row;
        uint4 vh = make_uint4(0u, 0u, 0u, 0u), vl = vh;
        if (grow < nrows) {
            vh = *(const uint4*)(Ahi + (size_t)grow * K + cb * 8);
            vl = *(const uint4*)(Alo + (size_t)grow * K + cb * 8);
        }
        *(uint4*)&Ah[row * KP + cb * 8] = vh;
        *(uint4*)&Al[row * KP + cb * 8] = vl;
    }
    // load B tile, convert fp32 -> hi/lo, store transposed [n][k]
    for (int idx = tid; idx < K * 64; idx += 256) {
        int k = idx >> 6, n = idx & 63;
        float v = 0.f;
        if (colBase + n < M) v = Wr[(size_t)k * M + colBase + n];
        __nv_bfloat16 h = __float2bfloat16(v);
        Bh[n * KP + k] = h;
        Bl[n * KP + k] = __float2bfloat16(v - __bfloat162float(h));
    }
    __syncthreads();

    const int warp = tid >> 5, lane = tid & 31;
    const int g = lane >> 2, t = lane & 3;
    const int mrow = warp * 16;
    const int jmax = min(8, (M - colBase + 7) / 8);

    float acc[8][4];
#pragma unroll
    for (int j = 0; j < 8; j++)
#pragma unroll
        for (int q = 0; q < 4; q++) acc[j][q] = 0.f;

    for (int ks = 0; ks < K / 16; ks++) {
        const int k0 = ks * 16;
        uint32_t ah[4], al_[4];
        const int a0 = (mrow + g) * KP + k0 + 2 * t;
        ah[0] = *(const uint32_t*)&Ah[a0];
        ah[1] = *(const uint32_t*)&Ah[a0 + 8 * KP];
        ah[2] = *(const uint32_t*)&Ah[a0 + 8];
        ah[3] = *(const uint32_t*)&Ah[a0 + 8 * KP + 8];
        al_[0] = *(const uint32_t*)&Al[a0];
        al_[1] = *(const uint32_t*)&Al[a0 + 8 * KP];
        al_[2] = *(const uint32_t*)&Al[a0 + 8];
        al_[3] = *(const uint32_t*)&Al[a0 + 8 * KP + 8];
#pragma unroll
        for (int j = 0; j < 8; j++) {
            if (j >= jmax) break;
            const int b0 = (j * 8 + g) * KP + k0 + 2 * t;
            uint32_t bh0 = *(const uint32_t*)&Bh[b0];
            uint32_t bh1 = *(const uint32_t*)&Bh[b0 + 8];
            uint32_t bl0 = *(const uint32_t*)&Bl[b0];
            uint32_t bl1 = *(const uint32_t*)&Bl[b0 + 8];
            mma16816(acc[j], ah, bh0, bh1);   // hi*hi
            mma16816(acc[j], al_, bh0, bh1);  // lo*hi
            mma16816(acc[j], ah, bl0, bl1);   // hi*lo
        }
    }

    // store
    const int row0 = rowBase + mrow + g;
#pragma unroll
    for (int j = 0; j < 8; j++) {
        if (j >= jmax) break;
        int col = colBase + j * 8 + 2 * t;
        if (col + 1 < M) {
            if (row0 < nrows) {
                float2 v = make_float2(acc[j][0], acc[j][1]);
                *(float2*)(Cr + (size_t)row0 * M + col) = v;
            }
            if (row0 + 8 < nrows) {
                float2 v = make_float2(acc[j][2], acc[j][3]);
                *(float2*)(Cr + (size_t)(row0 + 8) * M + col) = v;
            }
        }
    }
}

// ---------------- attention coefficients: el/er per (r,node,head) ----------
template <int HOUT>
__global__ void attn_k(const float* __restrict__ z, const float* __restrict__ al,
                       const float* __restrict__ ar, float* __restrict__ el,
                       float* __restrict__ er) {
    int w = (blockIdx.x * blockDim.x + threadIdx.x) >> 5;
    int lane = threadIdx.x & 31;
    if (w >= RR * NN) return;
    int r = w / NN;
    const int TOT = NH * HOUT;
    const float* zr = z + (size_t)w * TOT;
    float aL0 = 0, aL1 = 0, aL2 = 0, aR0 = 0, aR1 = 0, aR2 = 0;
    for (int j = lane; j < TOT; j += 32) {
        int h = j / HOUT, c = j % HOUT;
        float v = zr[j];
        float wl = al[((size_t)r * NH + h) * HOUT + c];
        float wr = ar[((size_t)r * NH + h) * HOUT + c];
        if (h == 0) { aL0 += v * wl; aR0 += v * wr; }
        else if (h == 1) { aL1 += v * wl; aR1 += v * wr; }
        else { aL2 += v * wl; aR2 += v * wr; }
    }
#pragma unroll
    for (int o = 16; o; o >>= 1) {
        aL0 += __shfl_xor_sync(0xffffffffu, aL0, o);
        aL1 += __shfl_xor_sync(0xffffffffu, aL1, o);
        aL2 += __shfl_xor_sync(0xffffffffu, aL2, o);
        aR0 += __shfl_xor_sync(0xffffffffu, aR0, o);
        aR1 += __shfl_xor_sync(0xffffffffu, aR1, o);
        aR2 += __shfl_xor_sync(0xffffffffu, aR2, o);
    }
    if (lane == 0) {
        size_t o = (size_t)w * NH;
        el[o] = aL0; el[o + 1] = aL1; el[o + 2] = aL2;
        er[o] = aR0; er[o + 1] = aR1; er[o + 2] = aR2;
    }
}

// ---------------- fused edge-softmax + aggregation + head/relation mean ----
template <int OUT, bool RELU>
__global__ void agg_k(const float* __restrict__ z, const float* __restrict__ el,
                      const float* __restrict__ er, const float* __restrict__ bias,
                      const int* __restrict__ ptr, const int* __restrict__ csrc,
                      float* __restrict__ out) {
    int w = (blockIdx.x * blockDim.x + threadIdx.x) >> 5;
    int lane = threadIdx.x & 31;
    if (w >= NN) return;
    const int n = w;
    float tot0 = 0.f, tot1 = 0.f;
    for (int r = 0; r < RR; r++) {
        const float* elr = el + (size_t)r * NN * NH;
        const float* ern = er + ((size_t)r * NN + n) * NH;
        float er0 = ern[0], er1 = ern[1], er2 = ern[2];
        int beg = ptr[r * (NN + 1) + n];
        int end = ptr[r * (NN + 1) + n + 1];
        const int* cs = csrc + (size_t)r * EE;

        float m0 = -1e30f, m1 = -1e30f, m2 = -1e30f;
        for (int i = beg + lane; i < end; i += 32) {
            const float* e3 = elr + (size_t)cs[i] * NH;
            m0 = fmaxf(m0, lrelu(e3[0] + er0));
            m1 = fmaxf(m1, lrelu(e3[1] + er1));
            m2 = fmaxf(m2, lrelu(e3[2] + er2));
        }
#pragma unroll
        for (int o = 16; o; o >>= 1) {
            m0 = fmaxf(m0, __shfl_xor_sync(0xffffffffu, m0, o));
            m1 = fmaxf(m1, __shfl_xor_sync(0xffffffffu, m1, o));
            m2 = fmaxf(m2, __shfl_xor_sync(0xffffffffu, m2, o));
        }
        float s0 = 0.f, s1 = 0.f, s2 = 0.f;
        for (int i = beg + lane; i < end; i += 32) {
            const float* e3 = elr + (size_t)cs[i] * NH;
            s0 += expf(lrelu(e3[0] + er0) - m0);
            s1 += expf(lrelu(e3[1] + er1) - m1);
            s2 += expf(lrelu(e3[2] + er2) - m2);
        }
#pragma unroll
        for (int o = 16; o; o >>= 1) {
            s0 += __shfl_xor_sync(0xffffffffu, s0, o);
            s1 += __shfl_xor_sync(0xffffffffu, s1, o);
            s2 += __shfl_xor_sync(0xffffffffu, s2, o);
        }
        float inv0 = (end > beg) ? 1.f / s0 : 0.f;
        float inv1 = (end > beg) ? 1.f / s1 : 0.f;
        float inv2 = (end > beg) ? 1.f / s2 : 0.f;

        float a00 = 0, a01 = 0, a10 = 0, a11 = 0, a20 = 0, a21 = 0;
        for (int i = beg; i < end; i++) {
            int s = cs[i];
            const float* e3 = elr + (size_t)s * NH;
            float al0 = expf(lrelu(e3[0] + er0) - m0) * inv0;
            float al1 = expf(lrelu(e3[1] + er1) - m1) * inv1;
            float al2 = expf(lrelu(e3[2] + er2) - m2) * inv2;
            const float* zr = z + ((size_t)r * NN + s) * (NH * OUT);
            a00 += al0 * zr[0 * OUT + lane];
            a10 += al1 * zr[1 * OUT + lane];
            a20 += al2 * zr[2 * OUT + lane];
            if (lane + 32 < OUT) {
                a01 += al0 * zr[0 * OUT + lane + 32];
                a11 += al1 * zr[1 * OUT + lane + 32];
                a21 += al2 * zr[2 * OUT + lane + 32];
            }
        }
        const float* br = bias + (size_t)r * NH * OUT;
        {
            float t0 = a00 + br[0 * OUT + lane];
            float t1 = a10 + br[1 * OUT + lane];
            float t2 = a20 + br[2 * OUT + lane];
            if (RELU) { t0 = fmaxf(t0, 0.f); t1 = fmaxf(t1, 0.f); t2 = fmaxf(t2, 0.f); }
            tot0 += (t0 + t1 + t2) * (1.f / NH);
        }
        if (lane + 32 < OUT) {
            float t0 = a01 + br[0 * OUT + lane + 32];
            float t1 = a11 + br[1 * OUT + lane + 32];
            float t2 = a21 + br[2 * OUT + lane + 32];
            if (RELU) { t0 = fmaxf(t0, 0.f); t1 = fmaxf(t1, 0.f); t2 = fmaxf(t2, 0.f); }
            tot1 += (t0 + t1 + t2) * (1.f / NH);
        }
    }
    out[(size_t)n * OUT + lane] = tot0 * (1.f / RR);
    if (lane + 32 < OUT) out[(size_t)n * OUT + lane + 32] = tot1 * (1.f / RR);
}

// ---------------- launch ----------------
extern "C" void kernel_launch(void* const* d_in, const int* in_sizes, int n_in,
                              void* d_out, int out_size) {
    const float* feat = (const float*)d_in[0];
    const int*   src  = (const int*)d_in[1];
    const int*   dst  = (const int*)d_in[2];
    const float* W1   = (const float*)d_in[3];
    const float* al1  = (const float*)d_in[4];
    const float* ar1  = (const float*)d_in[5];
    const float* b1   = (const float*)d_in[6];
    const float* W2   = (const float*)d_in[7];
    const float* al2  = (const float*)d_in[8];
    const float* ar2  = (const float*)d_in[9];
    const float* b2   = (const float*)d_in[10];
    float* out = (float*)d_out;

    unsigned char* base = nullptr;
    cudaGetSymbolAddress((void**)&base, g_scratch);

    size_t off = 0;
    auto carve = [&](size_t bytes) -> unsigned char* {
        unsigned char* p = base + off;
        off += (bytes + 255) & ~(size_t)255;
        return p;
    };
    float* z1  = (float*)carve((size_t)RR * NN * NH * FHID * 4);
    float* z2  = (float*)carve((size_t)RR * NN * NH * FC * 4);
    float* el1 = (float*)carve((size_t)RR * NN * NH * 4);
    float* er1 = (float*)carve((size_t)RR * NN * NH * 4);
    float* el2 = (float*)carve((size_t)RR * NN * NH * 4);
    float* er2 = (float*)carve((size_t)RR * NN * NH * 4);
    float* hbuf = (float*)carve((size_t)NN * FHID * 4);
    int* cnt  = (int*)carve((size_t)RR * NN * 4);
    int* ptr  = (int*)carve((size_t)RR * (NN + 1) * 4);
    int* cur  = (int*)carve((size_t)RR * NN * 4);
    int* csrc = (int*)carve((size_t)RR * EE * 4);
    __nv_bfloat16* fhi = (__nv_bfloat16*)carve((size_t)NN * FIN * 2);
    __nv_bfloat16* flo = (__nv_bfloat16*)carve((size_t)NN * FIN * 2);
    __nv_bfloat16* hhi = (__nv_bfloat16*)carve((size_t)NN * FHID * 2);
    __nv_bfloat16* hlo = (__nv_bfloat16*)carve((size_t)NN * FHID * 2);

    // dynamic smem sizes
    const int SMEM1 = (2 * 128 * (FIN + 8) + 2 * 64 * (FIN + 8)) * 2;   // K=128
    const int SMEM2 = (2 * 128 * (FHID + 8) + 2 * 64 * (FHID + 8)) * 2; // K=64
    cudaFuncSetAttribute(gemm_bf16_k<FIN>, cudaFuncAttributeMaxDynamicSharedMemorySize, SMEM1);
    cudaFuncSetAttribute(gemm_bf16_k<FHID>, cudaFuncAttributeMaxDynamicSharedMemorySize, SMEM2);

    // ---- CSR build (shared by both layers) ----
    zero_k<<<(RR * NN + 255) / 256, 256>>>(cnt, RR * NN);
    count_k<<<(RR * EE + 255) / 256, 256>>>(dst, cnt);
    scan_k<<<RR, 1024>>>(cnt, ptr, cur);
    scatter_k<<<(RR * EE + 255) / 256, 256>>>(src, dst, cur, csrc);

    // ---- layer 1 ----
    split_k<<<(NN * FIN / 4 + 255) / 256, 256>>>(feat, fhi, flo, NN * FIN / 4);
    {
        dim3 grid((NH * FHID + 63) / 64, (NN + 127) / 128, RR);
        gemm_bf16_k<FIN><<<grid, 256, SMEM1>>>(fhi, flo, W1, z1, NN, NH * FHID);
    }
    attn_k<FHID><<<(RR * NN * 32 + 255) / 256, 256>>>(z1, al1, ar1, el1, er1);
    agg_k<FHID, true><<<(NN * 32 + 255) / 256, 256>>>(z1, el1, er1, b1, ptr, csrc, hbuf);

    // ---- layer 2 ----
    split_k<<<(NN * FHID / 4 + 255) / 256, 256>>>(hbuf, hhi, hlo, NN * FHID / 4);
    {
        dim3 grid((NH * FC + 63) / 64, (NN + 127) / 128, RR);
        gemm_bf16_k<FHID><<<grid, 256, SMEM2>>>(hhi, hlo, W2, z2, NN, NH * FC);
    }
    attn_k<FC><<<(RR * NN * 32 + 255) / 256, 256>>>(z2, al2, ar2, el2, er2);
    agg_k<FC, false><<<(NN * 32 + 255) / 256, 256>>>(z2, el2, er2, b2, ptr, csrc, out);

    (void)in_sizes; (void)n_in; (void)out_size;
}